// round 8
// baseline (speedup 1.0000x reference)
#include <cuda_runtime.h>
#include <cstdint>

// ---------------------------------------------------------------------------
// AdjGenerator: adj = (mean_h sigmoid(log(relu(Wg·PE)+1e-6) + (q·kT)/32) > 0.5)
// N = M = 2048, D = 1024, EMB = 64, HEADS = 16
// ---------------------------------------------------------------------------

#define NDIM 2048
#define MDIM 2048
#define DDIM 1024
#define EMB  64
#define HEADS 16

__device__ float g_q[NDIM * DDIM];
__device__ float g_k[MDIM * DDIM];
__device__ float g_aff[NDIM * MDIM];

typedef unsigned long long ull;

// ---- packed f32x2 helpers (Blackwell FFMA2, PTX-only) ---------------------
__device__ __forceinline__ ull dup2(float v) {
    ull r;
    asm("mov.b64 %0, {%1, %1};" : "=l"(r) : "f"(v));
    return r;
}
__device__ __forceinline__ void fma2(ull& d, ull a, ull b) {
    asm("fma.rn.f32x2 %0, %1, %2, %0;" : "+l"(d) : "l"(a), "l"(b));
}
__device__ __forceinline__ float2 unpack2(ull v) {
    float2 f;
    asm("mov.b64 {%0, %1}, %2;" : "=f"(f.x), "=f"(f.y) : "l"(v));
    return f;
}
// streaming (evict-first) 16B global load
__device__ __forceinline__ void ldcs_v2u64(const void* p, ull& a, ull& b) {
    asm("ld.global.cs.v2.u64 {%0, %1}, [%2];" : "=l"(a), "=l"(b) : "l"(p));
}

// ---------------------------------------------------------------------------
// SGEMM NT: C[r,c] = scale * sum_d A[r,d]*B[c,d] + bias[c]
// 512 threads, BM=128, BN=256, BK=16, 8x8 per thread (16x32 thread grid).
// B microtile SPLIT into cols {tx*4..+3} and {128+tx*4..+3}: 16B lane stride
// -> conflict-free LDS.128 (the old tx*8 layout had 32B stride = 2-way
// conflicts, crossbar-bound at 288 cyc vs fma 256 per 16-warp k-step round).
// ---------------------------------------------------------------------------
#define BM 128
#define BN 256
#define BK 16
#define BH 128   /* BN/2 : offset of second column half */

__global__ void __launch_bounds__(512, 1)
gemm_nt_kernel(const float* __restrict__ A0, const float* __restrict__ B0,
               const float* __restrict__ bias0,
               const float* __restrict__ A1, const float* __restrict__ B1,
               const float* __restrict__ bias1,
               int Ncols, float scale, int outsel)
{
    const float* A;
    const float* B;
    const float* bias;
    float* C;
    if (outsel == 0) {
        if (blockIdx.z == 0) { A = A0; B = B0; bias = bias0; C = g_q; }
        else                 { A = A1; B = B1; bias = bias1; C = g_k; }
    } else {
        A = g_q; B = g_k; bias = nullptr; C = g_aff;
    }

    const int K = DDIM;

    __shared__ float As[BK][BM + 4];   //  8.4 KB
    __shared__ float Bs[BK][BN + 4];   // 16.6 KB

    const int tid = threadIdx.x;
    const int tx = tid & 31;        // 0..31 -> col pair {tx*4, 128+tx*4}
    const int ty = tid >> 5;        // 0..15 -> row block of 8
    const int row0 = blockIdx.y * BM;
    const int col0 = blockIdx.x * BN;

    const float* Abase = A + (size_t)row0 * K;
    const float* Bbase = B + (size_t)col0 * K;

    const int ar0 = tid >> 2,          ac0 = (tid & 3) * 4;         // A row 0..127
    const int br1 = (tid + 512) >> 2,  bc1 = ((tid + 512) & 3) * 4; // B row 128..255

    float4 av0 = *(const float4*)&Abase[(size_t)ar0 * K + ac0];
    float4 bv0 = *(const float4*)&Bbase[(size_t)ar0 * K + ac0];
    float4 bv1 = *(const float4*)&Bbase[(size_t)br1 * K + bc1];

    As[ac0 + 0][ar0] = av0.x; As[ac0 + 1][ar0] = av0.y;
    As[ac0 + 2][ar0] = av0.z; As[ac0 + 3][ar0] = av0.w;
    Bs[ac0 + 0][ar0] = bv0.x; Bs[ac0 + 1][ar0] = bv0.y;
    Bs[ac0 + 2][ar0] = bv0.z; Bs[ac0 + 3][ar0] = bv0.w;
    Bs[bc1 + 0][br1] = bv1.x; Bs[bc1 + 1][br1] = bv1.y;
    Bs[bc1 + 2][br1] = bv1.z; Bs[bc1 + 3][br1] = bv1.w;
    __syncthreads();

    ull c2[8][4];
#pragma unroll
    for (int i = 0; i < 8; i++)
#pragma unroll
        for (int j = 0; j < 4; j++) c2[i][j] = 0ull;

    for (int kc = BK; kc <= K; kc += BK) {
        if (kc < K) {
            av0 = *(const float4*)&Abase[(size_t)ar0 * K + kc + ac0];
            bv0 = *(const float4*)&Bbase[(size_t)ar0 * K + kc + ac0];
            bv1 = *(const float4*)&Bbase[(size_t)br1 * K + kc + bc1];
        }
#pragma unroll
        for (int k = 0; k < BK; k++) {
            float4 aA = *(const float4*)&As[k][ty * 8];
            float4 aB = *(const float4*)&As[k][ty * 8 + 4];
            ull a2[8];
            a2[0] = dup2(aA.x); a2[1] = dup2(aA.y); a2[2] = dup2(aA.z); a2[3] = dup2(aA.w);
            a2[4] = dup2(aB.x); a2[5] = dup2(aB.y); a2[6] = dup2(aB.z); a2[7] = dup2(aB.w);
            // conflict-free: 16B lane stride in both halves
            ulonglong2 b01 = *(const ulonglong2*)&Bs[k][tx * 4];
            ulonglong2 b23 = *(const ulonglong2*)&Bs[k][BH + tx * 4];
            ull b2[4] = { b01.x, b01.y, b23.x, b23.y };
#pragma unroll
            for (int i = 0; i < 8; i++) {
#pragma unroll
                for (int j = 0; j < 4; j++) fma2(c2[i][j], a2[i], b2[j]);
            }
        }
        if (kc < K) {
            __syncthreads();
            As[ac0 + 0][ar0] = av0.x; As[ac0 + 1][ar0] = av0.y;
            As[ac0 + 2][ar0] = av0.z; As[ac0 + 3][ar0] = av0.w;
            Bs[ac0 + 0][ar0] = bv0.x; Bs[ac0 + 1][ar0] = bv0.y;
            Bs[ac0 + 2][ar0] = bv0.z; Bs[ac0 + 3][ar0] = bv0.w;
            Bs[bc1 + 0][br1] = bv1.x; Bs[bc1 + 1][br1] = bv1.y;
            Bs[bc1 + 2][br1] = bv1.z; Bs[bc1 + 3][br1] = bv1.w;
            __syncthreads();
        }
    }

    // epilogue: two float4 stores per row, halves 128 cols apart (coalesced)
#pragma unroll
    for (int i = 0; i < 8; i++) {
        size_t r = (size_t)(row0 + ty * 8 + i);
        float* crow = C + r * (size_t)Ncols + col0;
        float2 f0 = unpack2(c2[i][0]);
        float2 f1 = unpack2(c2[i][1]);
        float2 f2v = unpack2(c2[i][2]);
        float2 f3 = unpack2(c2[i][3]);
        float4 o0, o1;
        if (bias) {
            const float* bp0 = bias + col0 + tx * 4;
            const float* bp1 = bias + col0 + BH + tx * 4;
            o0 = make_float4(f0.x * scale + bp0[0], f0.y * scale + bp0[1],
                             f1.x * scale + bp0[2], f1.y * scale + bp0[3]);
            o1 = make_float4(f2v.x * scale + bp1[0], f2v.y * scale + bp1[1],
                             f3.x * scale + bp1[2], f3.y * scale + bp1[3]);
        } else {
            o0 = make_float4(f0.x * scale, f0.y * scale, f1.x * scale, f1.y * scale);
            o1 = make_float4(f2v.x * scale, f2v.y * scale, f3.x * scale, f3.y * scale);
        }
        *(float4*)&crow[tx * 4]      = o0;
        *(float4*)&crow[BH + tx * 4] = o1;
    }
}

// ---------------------------------------------------------------------------
// Pos-gate stream + fused epilogue (unchanged — near HBM limit).
// ---------------------------------------------------------------------------
__global__ void __launch_bounds__(256, 2)
pos_epilogue_kernel(const float* __restrict__ PE, const float* __restrict__ Wg_w,
                    const float* __restrict__ Wg_b, float* __restrict__ out)
{
    __shared__ ull sh_wg2[EMB][HEADS];   // dup'd f32x2 per (e, h), 8 KB
    __shared__ float sh_b[HEADS];

    const int tid = threadIdx.x;
    for (int idx = tid; idx < EMB * HEADS; idx += 256) {
        int e = idx >> 4, h = idx & 15;
        sh_wg2[e][h] = dup2(Wg_w[h * EMB + e]);
    }
    if (tid < HEADS) sh_b[tid] = Wg_b[tid];
    __syncthreads();

    const int n = blockIdx.y;
    const int m = blockIdx.x * 1024 + tid * 4;

    const char* pe = (const char*)(PE + (size_t)n * MDIM + m);
    const size_t PLANE = (size_t)NDIM * MDIM * 4;   // bytes

    ull acc[HEADS][2];
#pragma unroll
    for (int h = 0; h < HEADS; h++) { acc[h][0] = 0ull; acc[h][1] = 0ull; }

    ull bx[4], by[4];
#pragma unroll
    for (int i = 0; i < 4; i++) ldcs_v2u64(pe + (size_t)i * PLANE, bx[i], by[i]);

    for (int eo = 0; eo < EMB; eo += 4) {
#pragma unroll
        for (int i = 0; i < 4; i++) {
            ull pvx = bx[i], pvy = by[i];
            int en_ = eo + 4 + i;
            if (en_ < EMB) ldcs_v2u64(pe + (size_t)en_ * PLANE, bx[i], by[i]);
            const ulonglong2* wrow = (const ulonglong2*)sh_wg2[eo + i];
#pragma unroll
            for (int h2 = 0; h2 < 8; h2++) {
                ulonglong2 w = wrow[h2];          // LDS.128: 2 heads
                fma2(acc[2 * h2][0],     w.x, pvx);
                fma2(acc[2 * h2][1],     w.x, pvy);
                fma2(acc[2 * h2 + 1][0], w.y, pvx);
                fma2(acc[2 * h2 + 1][1], w.y, pvy);
            }
        }
    }

    const float4 av = *(const float4*)&g_aff[(size_t)n * MDIM + m];
    const float L2E = 1.4426950408889634f;
    float en0 = exp2f(-av.x * L2E);
    float en1 = exp2f(-av.y * L2E);
    float en2 = exp2f(-av.z * L2E);
    float en3 = exp2f(-av.w * L2E);

    float s0 = 0.f, s1 = 0.f, s2 = 0.f, s3 = 0.f;
#pragma unroll
    for (int h = 0; h < HEADS; h++) {
        float bh = sh_b[h];
        float2 p0 = unpack2(acc[h][0]);
        float2 p1 = unpack2(acc[h][1]);
        float w;
        w = fmaxf(p0.x + bh, 0.f) + 1e-6f; s0 += __fdividef(w, w + en0);
        w = fmaxf(p0.y + bh, 0.f) + 1e-6f; s1 += __fdividef(w, w + en1);
        w = fmaxf(p1.x + bh, 0.f) + 1e-6f; s2 += __fdividef(w, w + en2);
        w = fmaxf(p1.y + bh, 0.f) + 1e-6f; s3 += __fdividef(w, w + en3);
    }

    float4 o;
    o.x = (s0 > 8.0f) ? 1.0f : 0.0f;
    o.y = (s1 > 8.0f) ? 1.0f : 0.0f;
    o.z = (s2 > 8.0f) ? 1.0f : 0.0f;
    o.w = (s3 > 8.0f) ? 1.0f : 0.0f;
    *(float4*)&out[(size_t)n * MDIM + m] = o;
}

// ---------------------------------------------------------------------------
extern "C" void kernel_launch(void* const* d_in, const int* in_sizes, int n_in,
                              void* d_out, int out_size)
{
    (void)in_sizes; (void)n_in; (void)out_size;
    const float* ref_feat = (const float*)d_in[0];
    const float* sup_feat = (const float*)d_in[1];
    const float* PE       = (const float*)d_in[2];
    const float* Wg_w     = (const float*)d_in[3];
    const float* Wg_b     = (const float*)d_in[4];
    const float* Wq_w     = (const float*)d_in[5];
    const float* Wq_b     = (const float*)d_in[6];
    const float* Wk_w     = (const float*)d_in[7];
    const float* Wk_b     = (const float*)d_in[8];
    float* out = (float*)d_out;

    // fused q/k GEMM: z=0 -> q = ref@WqT+bq, z=1 -> k = sup@WkT+bk
    gemm_nt_kernel<<<dim3(DDIM / BN, NDIM / BM, 2), 512>>>(
        ref_feat, Wq_w, Wq_b, sup_feat, Wk_w, Wk_b, DDIM, 1.0f, 0);
    // aff = (q @ kT) / 32
    gemm_nt_kernel<<<dim3(MDIM / BN, NDIM / BM, 1), 512>>>(
        nullptr, nullptr, nullptr, nullptr, nullptr, nullptr, MDIM, 0.03125f, 2);
    // pos stream + fused epilogue
    pos_epilogue_kernel<<<dim3(MDIM / 1024, NDIM), 256>>>(PE, Wg_w, Wg_b, out);
}

// round 9
// speedup vs baseline: 1.4189x; 1.4189x over previous
#include <cuda_runtime.h>
#include <cstdint>

// ---------------------------------------------------------------------------
// AdjGenerator: adj = (mean_h sigmoid(log(relu(Wg·PE)+1e-6) + (q·kT)/32) > 0.5)
// N = M = 2048, D = 1024, EMB = 64, HEADS = 16
// ---------------------------------------------------------------------------

#define NDIM 2048
#define MDIM 2048
#define DDIM 1024
#define EMB  64
#define HEADS 16

__device__ float g_q[NDIM * DDIM];
__device__ float g_k[MDIM * DDIM];
__device__ float g_aff[NDIM * MDIM];

typedef unsigned long long ull;

// ---- packed f32x2 helpers (Blackwell FFMA2, PTX-only) ---------------------
__device__ __forceinline__ ull dup2(float v) {
    ull r;
    asm("mov.b64 %0, {%1, %1};" : "=l"(r) : "f"(v));
    return r;
}
__device__ __forceinline__ void fma2(ull& d, ull a, ull b) {
    asm("fma.rn.f32x2 %0, %1, %2, %0;" : "+l"(d) : "l"(a), "l"(b));
}
__device__ __forceinline__ float2 unpack2(ull v) {
    float2 f;
    asm("mov.b64 {%0, %1}, %2;" : "=f"(f.x), "=f"(f.y) : "l"(v));
    return f;
}
// streaming (evict-first) 16B global load
__device__ __forceinline__ void ldcs_v2u64(const void* p, ull& a, ull& b) {
    asm("ld.global.cs.v2.u64 {%0, %1}, [%2];" : "=l"(a), "=l"(b) : "l"(p));
}

// ---------------------------------------------------------------------------
// SGEMM NT: C[r,c] = scale * sum_d A[r,d]*B[c,d] + bias[c]
// 512 threads, BM=128, BN=256, BK=16, 8 rows x 8 cols per thread.
// ROW-PACKED accumulators: c2[i2][j] = f32x2{row 2*i2, row 2*i2+1} x col j.
//   - A fragment: plain LDS.128 of adjacent rows -> pre-packed pairs, NO movs.
//   - B stored PRE-DUPLICATED (ull) in SMEM; dup cost paid once per chunk fill.
//   - B cols in 4 groups {0,64,128,192}+tx*2 -> 16B lane stride, conflict-free.
// Double-buffered SMEM: one __syncthreads per BK chunk.
// ---------------------------------------------------------------------------
#define BM 128
#define BN 256
#define BK 16
#define NCHUNK (DDIM / BK)

__global__ void __launch_bounds__(512, 1)
gemm_nt_kernel(const float* __restrict__ A0, const float* __restrict__ B0,
               const float* __restrict__ bias0,
               const float* __restrict__ A1, const float* __restrict__ B1,
               const float* __restrict__ bias1,
               int Ncols, float scale, int outsel)
{
    const float* A;
    const float* B;
    const float* bias;
    float* C;
    if (outsel == 0) {
        if (blockIdx.z == 0) { A = A0; B = B0; bias = bias0; C = g_q; }
        else                 { A = A1; B = B1; bias = bias1; C = g_k; }
    } else {
        A = g_q; B = g_k; bias = nullptr; C = g_aff;
    }

    const int K = DDIM;

    __shared__ float As[2][BK][BM + 4];    // 16.9 KB
    __shared__ ull   Bsd[2][BK][BN + 2];   // 66.0 KB (pre-dup'd, 16B-aligned rows)

    const int tid = threadIdx.x;
    const int tx = tid & 31;        // 0..31 -> col pairs {g*64 + tx*2}
    const int ty = tid >> 5;        // 0..15 -> 8-row block
    const int row0 = blockIdx.y * BM;
    const int col0 = blockIdx.x * BN;

    const float* Abase = A + (size_t)row0 * K;
    const float* Bbase = B + (size_t)col0 * K;

    // fill mapping: A 512 float4 slots (1/thread), B 1024 slots (2/thread)
    const int ar0 = tid >> 2,          ac0 = (tid & 3) * 4;         // rows 0..127
    const int br1 = (tid + 512) >> 2,  bc1 = ((tid + 512) & 3) * 4; // B rows 128..255

    float4 av0 = *(const float4*)&Abase[(size_t)ar0 * K + ac0];
    float4 bv0 = *(const float4*)&Bbase[(size_t)ar0 * K + ac0];
    float4 bv1 = *(const float4*)&Bbase[(size_t)br1 * K + bc1];

    As[0][ac0 + 0][ar0] = av0.x; As[0][ac0 + 1][ar0] = av0.y;
    As[0][ac0 + 2][ar0] = av0.z; As[0][ac0 + 3][ar0] = av0.w;
    Bsd[0][ac0 + 0][ar0] = dup2(bv0.x); Bsd[0][ac0 + 1][ar0] = dup2(bv0.y);
    Bsd[0][ac0 + 2][ar0] = dup2(bv0.z); Bsd[0][ac0 + 3][ar0] = dup2(bv0.w);
    Bsd[0][bc1 + 0][br1] = dup2(bv1.x); Bsd[0][bc1 + 1][br1] = dup2(bv1.y);
    Bsd[0][bc1 + 2][br1] = dup2(bv1.z); Bsd[0][bc1 + 3][br1] = dup2(bv1.w);
    __syncthreads();

    ull c2[4][8];   // [row-pair][col]
#pragma unroll
    for (int i = 0; i < 4; i++)
#pragma unroll
        for (int j = 0; j < 8; j++) c2[i][j] = 0ull;

    int s = 0;
    for (int c = 0; c < NCHUNK; c++) {
        const int kc = (c + 1) * BK;
        if (c + 1 < NCHUNK) {
            av0 = *(const float4*)&Abase[(size_t)ar0 * K + kc + ac0];
            bv0 = *(const float4*)&Bbase[(size_t)ar0 * K + kc + ac0];
            bv1 = *(const float4*)&Bbase[(size_t)br1 * K + kc + bc1];
        }
#pragma unroll
        for (int k = 0; k < BK; k++) {
            // A: 8 adjacent rows = 4 packed pairs, 2x LDS.128 (broadcast)
            ulonglong2 aA = *(const ulonglong2*)&As[s][k][ty * 8];
            ulonglong2 aB = *(const ulonglong2*)&As[s][k][ty * 8 + 4];
            ull a2[4] = { aA.x, aA.y, aB.x, aB.y };
            // B: 8 dup'd cols in 4 groups, 4x LDS.128 (16B lane stride)
            ulonglong2 b01 = *(const ulonglong2*)&Bsd[s][k][tx * 2];
            ulonglong2 b23 = *(const ulonglong2*)&Bsd[s][k][64 + tx * 2];
            ulonglong2 b45 = *(const ulonglong2*)&Bsd[s][k][128 + tx * 2];
            ulonglong2 b67 = *(const ulonglong2*)&Bsd[s][k][192 + tx * 2];
            ull b2[8] = { b01.x, b01.y, b23.x, b23.y, b45.x, b45.y, b67.x, b67.y };
#pragma unroll
            for (int i = 0; i < 4; i++) {
#pragma unroll
                for (int j = 0; j < 8; j++) fma2(c2[i][j], a2[i], b2[j]);
            }
        }
        if (c + 1 < NCHUNK) {
            const int t = s ^ 1;
            As[t][ac0 + 0][ar0] = av0.x; As[t][ac0 + 1][ar0] = av0.y;
            As[t][ac0 + 2][ar0] = av0.z; As[t][ac0 + 3][ar0] = av0.w;
            Bsd[t][ac0 + 0][ar0] = dup2(bv0.x); Bsd[t][ac0 + 1][ar0] = dup2(bv0.y);
            Bsd[t][ac0 + 2][ar0] = dup2(bv0.z); Bsd[t][ac0 + 3][ar0] = dup2(bv0.w);
            Bsd[t][bc1 + 0][br1] = dup2(bv1.x); Bsd[t][bc1 + 1][br1] = dup2(bv1.y);
            Bsd[t][bc1 + 2][br1] = dup2(bv1.z); Bsd[t][bc1 + 3][br1] = dup2(bv1.w);
            __syncthreads();
            s = t;
        }
    }

    // epilogue: rows in pairs; cols in 4 groups of 2 (float2 stores)
    float2 bv[4];
    if (bias) {
#pragma unroll
        for (int g = 0; g < 4; g++)
            bv[g] = *(const float2*)&bias[col0 + g * 64 + tx * 2];
    }
#pragma unroll
    for (int i2 = 0; i2 < 4; i2++) {
        size_t r = (size_t)(row0 + ty * 8 + 2 * i2);
        float* rlo = C + r * (size_t)Ncols + col0;
        float* rhi = rlo + Ncols;
#pragma unroll
        for (int g = 0; g < 4; g++) {
            float2 pa = unpack2(c2[i2][2 * g]);       // col g*64+tx*2
            float2 pb = unpack2(c2[i2][2 * g + 1]);   // col g*64+tx*2+1
            float2 olo, ohi;
            if (bias) {
                olo = make_float2(pa.x * scale + bv[g].x, pb.x * scale + bv[g].y);
                ohi = make_float2(pa.y * scale + bv[g].x, pb.y * scale + bv[g].y);
            } else {
                olo = make_float2(pa.x * scale, pb.x * scale);
                ohi = make_float2(pa.y * scale, pb.y * scale);
            }
            *(float2*)&rlo[g * 64 + tx * 2] = olo;
            *(float2*)&rhi[g * 64 + tx * 2] = ohi;
        }
    }
}

// ---------------------------------------------------------------------------
// Pos-gate stream + fused epilogue (unchanged — near HBM limit).
// ---------------------------------------------------------------------------
__global__ void __launch_bounds__(256, 2)
pos_epilogue_kernel(const float* __restrict__ PE, const float* __restrict__ Wg_w,
                    const float* __restrict__ Wg_b, float* __restrict__ out)
{
    __shared__ ull sh_wg2[EMB][HEADS];   // dup'd f32x2 per (e, h), 8 KB
    __shared__ float sh_b[HEADS];

    const int tid = threadIdx.x;
    for (int idx = tid; idx < EMB * HEADS; idx += 256) {
        int e = idx >> 4, h = idx & 15;
        sh_wg2[e][h] = dup2(Wg_w[h * EMB + e]);
    }
    if (tid < HEADS) sh_b[tid] = Wg_b[tid];
    __syncthreads();

    const int n = blockIdx.y;
    const int m = blockIdx.x * 1024 + tid * 4;

    const char* pe = (const char*)(PE + (size_t)n * MDIM + m);
    const size_t PLANE = (size_t)NDIM * MDIM * 4;   // bytes

    ull acc[HEADS][2];
#pragma unroll
    for (int h = 0; h < HEADS; h++) { acc[h][0] = 0ull; acc[h][1] = 0ull; }

    ull bx[4], by[4];
#pragma unroll
    for (int i = 0; i < 4; i++) ldcs_v2u64(pe + (size_t)i * PLANE, bx[i], by[i]);

    for (int eo = 0; eo < EMB; eo += 4) {
#pragma unroll
        for (int i = 0; i < 4; i++) {
            ull pvx = bx[i], pvy = by[i];
            int en_ = eo + 4 + i;
            if (en_ < EMB) ldcs_v2u64(pe + (size_t)en_ * PLANE, bx[i], by[i]);
            const ulonglong2* wrow = (const ulonglong2*)sh_wg2[eo + i];
#pragma unroll
            for (int h2 = 0; h2 < 8; h2++) {
                ulonglong2 w = wrow[h2];          // LDS.128: 2 heads
                fma2(acc[2 * h2][0],     w.x, pvx);
                fma2(acc[2 * h2][1],     w.x, pvy);
                fma2(acc[2 * h2 + 1][0], w.y, pvx);
                fma2(acc[2 * h2 + 1][1], w.y, pvy);
            }
        }
    }

    const float4 av = *(const float4*)&g_aff[(size_t)n * MDIM + m];
    const float L2E = 1.4426950408889634f;
    float en0 = exp2f(-av.x * L2E);
    float en1 = exp2f(-av.y * L2E);
    float en2 = exp2f(-av.z * L2E);
    float en3 = exp2f(-av.w * L2E);

    float s0 = 0.f, s1 = 0.f, s2 = 0.f, s3 = 0.f;
#pragma unroll
    for (int h = 0; h < HEADS; h++) {
        float bh = sh_b[h];
        float2 p0 = unpack2(acc[h][0]);
        float2 p1 = unpack2(acc[h][1]);
        float w;
        w = fmaxf(p0.x + bh, 0.f) + 1e-6f; s0 += __fdividef(w, w + en0);
        w = fmaxf(p0.y + bh, 0.f) + 1e-6f; s1 += __fdividef(w, w + en1);
        w = fmaxf(p1.x + bh, 0.f) + 1e-6f; s2 += __fdividef(w, w + en2);
        w = fmaxf(p1.y + bh, 0.f) + 1e-6f; s3 += __fdividef(w, w + en3);
    }

    float4 o;
    o.x = (s0 > 8.0f) ? 1.0f : 0.0f;
    o.y = (s1 > 8.0f) ? 1.0f : 0.0f;
    o.z = (s2 > 8.0f) ? 1.0f : 0.0f;
    o.w = (s3 > 8.0f) ? 1.0f : 0.0f;
    *(float4*)&out[(size_t)n * MDIM + m] = o;
}

// ---------------------------------------------------------------------------
extern "C" void kernel_launch(void* const* d_in, const int* in_sizes, int n_in,
                              void* d_out, int out_size)
{
    (void)in_sizes; (void)n_in; (void)out_size;
    const float* ref_feat = (const float*)d_in[0];
    const float* sup_feat = (const float*)d_in[1];
    const float* PE       = (const float*)d_in[2];
    const float* Wg_w     = (const float*)d_in[3];
    const float* Wg_b     = (const float*)d_in[4];
    const float* Wq_w     = (const float*)d_in[5];
    const float* Wq_b     = (const float*)d_in[6];
    const float* Wk_w     = (const float*)d_in[7];
    const float* Wk_b     = (const float*)d_in[8];
    float* out = (float*)d_out;

    // fused q/k GEMM: z=0 -> q = ref@WqT+bq, z=1 -> k = sup@WkT+bk
    gemm_nt_kernel<<<dim3(DDIM / BN, NDIM / BM, 2), 512>>>(
        ref_feat, Wq_w, Wq_b, sup_feat, Wk_w, Wk_b, DDIM, 1.0f, 0);
    // aff = (q @ kT) / 32
    gemm_nt_kernel<<<dim3(MDIM / BN, NDIM / BM, 1), 512>>>(
        nullptr, nullptr, nullptr, nullptr, nullptr, nullptr, MDIM, 0.03125f, 2);
    // pos stream + fused epilogue
    pos_epilogue_kernel<<<dim3(MDIM / 1024, NDIM), 256>>>(PE, Wg_w, Wg_b, out);
}

// round 10
// speedup vs baseline: 1.6282x; 1.1475x over previous
#include <cuda_runtime.h>
#include <cstdint>

// ---------------------------------------------------------------------------
// AdjGenerator: adj = (mean_h sigmoid(log(relu(Wg·PE)+1e-6) + (q·kT)/32) > 0.5)
// N = M = 2048, D = 1024, EMB = 64, HEADS = 16
// ---------------------------------------------------------------------------

#define NDIM 2048
#define MDIM 2048
#define DDIM 1024
#define EMB  64
#define HEADS 16

__device__ float g_q[NDIM * DDIM];
__device__ float g_k[MDIM * DDIM];
__device__ float g_aff[NDIM * MDIM];

typedef unsigned long long ull;

// ---- packed f32x2 helpers (Blackwell FFMA2, PTX-only) ---------------------
__device__ __forceinline__ ull dup2(float v) {
    ull r;
    asm("mov.b64 %0, {%1, %1};" : "=l"(r) : "f"(v));
    return r;
}
__device__ __forceinline__ void fma2(ull& d, ull a, ull b) {
    asm("fma.rn.f32x2 %0, %1, %2, %0;" : "+l"(d) : "l"(a), "l"(b));
}
__device__ __forceinline__ float2 unpack2(ull v) {
    float2 f;
    asm("mov.b64 {%0, %1}, %2;" : "=f"(f.x), "=f"(f.y) : "l"(v));
    return f;
}
// streaming (evict-first) 16B global load
__device__ __forceinline__ void ldcs_v2u64(const void* p, ull& a, ull& b) {
    asm("ld.global.cs.v2.u64 {%0, %1}, [%2];" : "=l"(a), "=l"(b) : "l"(p));
}

// ---------------------------------------------------------------------------
// SGEMM NT: C[r,c] = scale * sum_d A[r,d]*B[c,d] + bias[c]
// 512 threads, BM=128, BN=256, BK=16, 8 rows x 8 cols per thread.
// ROW-PACKED accumulators: c2[i2][j] = f32x2{row 2*i2, row 2*i2+1} x col j.
//   - A fragment: 2 broadcast LDS.128 of adjacent rows -> pre-packed pairs.
//   - B fragment: FLOAT smem (crossbar-cheap), 2 conflict-free LDS.128
//     (cols {tx*4..+3} and {128+tx*4..+3}); dup'd in regs (8 alu MOVs,
//     no fma-pipe contention). Crossbar ~132 cyc/round << fma 256.
// Double-buffered SMEM (50 KB): one __syncthreads per BK chunk.
// ---------------------------------------------------------------------------
#define BM 128
#define BN 256
#define BK 16
#define BH 128   /* BN/2 */
#define NCHUNK (DDIM / BK)

__global__ void __launch_bounds__(512, 1)
gemm_nt_kernel(const float* __restrict__ A0, const float* __restrict__ B0,
               const float* __restrict__ bias0,
               const float* __restrict__ A1, const float* __restrict__ B1,
               const float* __restrict__ bias1,
               int Ncols, float scale, int outsel)
{
    const float* A;
    const float* B;
    const float* bias;
    float* C;
    if (outsel == 0) {
        if (blockIdx.z == 0) { A = A0; B = B0; bias = bias0; C = g_q; }
        else                 { A = A1; B = B1; bias = bias1; C = g_k; }
    } else {
        A = g_q; B = g_k; bias = nullptr; C = g_aff;
    }

    const int K = DDIM;

    __shared__ float As[2][BK][BM + 4];   // 16.9 KB
    __shared__ float Bs[2][BK][BN + 4];   // 33.3 KB

    const int tid = threadIdx.x;
    const int tx = tid & 31;        // 0..31 -> col halves {tx*4, 128+tx*4}
    const int ty = tid >> 5;        // 0..15 -> 8-row block
    const int row0 = blockIdx.y * BM;
    const int col0 = blockIdx.x * BN;

    const float* Abase = A + (size_t)row0 * K;
    const float* Bbase = B + (size_t)col0 * K;

    const int ar0 = tid >> 2,          ac0 = (tid & 3) * 4;         // rows 0..127
    const int br1 = (tid + 512) >> 2,  bc1 = ((tid + 512) & 3) * 4; // B rows 128..255

    float4 av0 = *(const float4*)&Abase[(size_t)ar0 * K + ac0];
    float4 bv0 = *(const float4*)&Bbase[(size_t)ar0 * K + ac0];
    float4 bv1 = *(const float4*)&Bbase[(size_t)br1 * K + bc1];

    As[0][ac0 + 0][ar0] = av0.x; As[0][ac0 + 1][ar0] = av0.y;
    As[0][ac0 + 2][ar0] = av0.z; As[0][ac0 + 3][ar0] = av0.w;
    Bs[0][ac0 + 0][ar0] = bv0.x; Bs[0][ac0 + 1][ar0] = bv0.y;
    Bs[0][ac0 + 2][ar0] = bv0.z; Bs[0][ac0 + 3][ar0] = bv0.w;
    Bs[0][bc1 + 0][br1] = bv1.x; Bs[0][bc1 + 1][br1] = bv1.y;
    Bs[0][bc1 + 2][br1] = bv1.z; Bs[0][bc1 + 3][br1] = bv1.w;
    __syncthreads();

    ull c2[4][8];   // [row-pair][col]
#pragma unroll
    for (int i = 0; i < 4; i++)
#pragma unroll
        for (int j = 0; j < 8; j++) c2[i][j] = 0ull;

    int s = 0;
    for (int c = 0; c < NCHUNK; c++) {
        const int kc = (c + 1) * BK;
        if (c + 1 < NCHUNK) {
            av0 = *(const float4*)&Abase[(size_t)ar0 * K + kc + ac0];
            bv0 = *(const float4*)&Bbase[(size_t)ar0 * K + kc + ac0];
            bv1 = *(const float4*)&Bbase[(size_t)br1 * K + kc + bc1];
        }
#pragma unroll
        for (int k = 0; k < BK; k++) {
            // A: 8 adjacent rows = 4 packed pairs, 2x broadcast LDS.128
            ulonglong2 aA = *(const ulonglong2*)&As[s][k][ty * 8];
            ulonglong2 aB = *(const ulonglong2*)&As[s][k][ty * 8 + 4];
            ull a2[4] = { aA.x, aA.y, aB.x, aB.y };
            // B: 8 float cols, 2 conflict-free LDS.128, dup'd in regs (alu)
            float4 f0 = *(const float4*)&Bs[s][k][tx * 4];
            float4 f1 = *(const float4*)&Bs[s][k][BH + tx * 4];
            ull b2[8];
            b2[0] = dup2(f0.x); b2[1] = dup2(f0.y); b2[2] = dup2(f0.z); b2[3] = dup2(f0.w);
            b2[4] = dup2(f1.x); b2[5] = dup2(f1.y); b2[6] = dup2(f1.z); b2[7] = dup2(f1.w);
#pragma unroll
            for (int i = 0; i < 4; i++) {
#pragma unroll
                for (int j = 0; j < 8; j++) fma2(c2[i][j], a2[i], b2[j]);
            }
        }
        if (c + 1 < NCHUNK) {
            const int t = s ^ 1;
            As[t][ac0 + 0][ar0] = av0.x; As[t][ac0 + 1][ar0] = av0.y;
            As[t][ac0 + 2][ar0] = av0.z; As[t][ac0 + 3][ar0] = av0.w;
            Bs[t][ac0 + 0][ar0] = bv0.x; Bs[t][ac0 + 1][ar0] = bv0.y;
            Bs[t][ac0 + 2][ar0] = bv0.z; Bs[t][ac0 + 3][ar0] = bv0.w;
            Bs[t][bc1 + 0][br1] = bv1.x; Bs[t][bc1 + 1][br1] = bv1.y;
            Bs[t][bc1 + 2][br1] = bv1.z; Bs[t][bc1 + 3][br1] = bv1.w;
            __syncthreads();
            s = t;
        }
    }

    // epilogue: row pairs; per row, float4 per column half
    float4 bv_lo, bv_hi;
    if (bias) {
        bv_lo = *(const float4*)&bias[col0 + tx * 4];
        bv_hi = *(const float4*)&bias[col0 + BH + tx * 4];
    }
#pragma unroll
    for (int i2 = 0; i2 < 4; i2++) {
        size_t r = (size_t)(row0 + ty * 8 + 2 * i2);
        float* rlo = C + r * (size_t)Ncols + col0;
        float* rhi = rlo + Ncols;
        float2 p0 = unpack2(c2[i2][0]);
        float2 p1 = unpack2(c2[i2][1]);
        float2 p2 = unpack2(c2[i2][2]);
        float2 p3 = unpack2(c2[i2][3]);
        float2 p4 = unpack2(c2[i2][4]);
        float2 p5 = unpack2(c2[i2][5]);
        float2 p6 = unpack2(c2[i2][6]);
        float2 p7 = unpack2(c2[i2][7]);
        float4 lo0, lo1, hi0, hi1;
        if (bias) {
            lo0 = make_float4(p0.x * scale + bv_lo.x, p1.x * scale + bv_lo.y,
                              p2.x * scale + bv_lo.z, p3.x * scale + bv_lo.w);
            hi0 = make_float4(p0.y * scale + bv_lo.x, p1.y * scale + bv_lo.y,
                              p2.y * scale + bv_lo.z, p3.y * scale + bv_lo.w);
            lo1 = make_float4(p4.x * scale + bv_hi.x, p5.x * scale + bv_hi.y,
                              p6.x * scale + bv_hi.z, p7.x * scale + bv_hi.w);
            hi1 = make_float4(p4.y * scale + bv_hi.x, p5.y * scale + bv_hi.y,
                              p6.y * scale + bv_hi.z, p7.y * scale + bv_hi.w);
        } else {
            lo0 = make_float4(p0.x * scale, p1.x * scale, p2.x * scale, p3.x * scale);
            hi0 = make_float4(p0.y * scale, p1.y * scale, p2.y * scale, p3.y * scale);
            lo1 = make_float4(p4.x * scale, p5.x * scale, p6.x * scale, p7.x * scale);
            hi1 = make_float4(p4.y * scale, p5.y * scale, p6.y * scale, p7.y * scale);
        }
        *(float4*)&rlo[tx * 4]      = lo0;
        *(float4*)&rlo[BH + tx * 4] = lo1;
        *(float4*)&rhi[tx * 4]      = hi0;
        *(float4*)&rhi[BH + tx * 4] = hi1;
    }
}

// ---------------------------------------------------------------------------
// Pos-gate stream + fused epilogue (unchanged — near HBM limit).
// ---------------------------------------------------------------------------
__global__ void __launch_bounds__(256, 2)
pos_epilogue_kernel(const float* __restrict__ PE, const float* __restrict__ Wg_w,
                    const float* __restrict__ Wg_b, float* __restrict__ out)
{
    __shared__ ull sh_wg2[EMB][HEADS];   // dup'd f32x2 per (e, h), 8 KB
    __shared__ float sh_b[HEADS];

    const int tid = threadIdx.x;
    for (int idx = tid; idx < EMB * HEADS; idx += 256) {
        int e = idx >> 4, h = idx & 15;
        sh_wg2[e][h] = dup2(Wg_w[h * EMB + e]);
    }
    if (tid < HEADS) sh_b[tid] = Wg_b[tid];
    __syncthreads();

    const int n = blockIdx.y;
    const int m = blockIdx.x * 1024 + tid * 4;

    const char* pe = (const char*)(PE + (size_t)n * MDIM + m);
    const size_t PLANE = (size_t)NDIM * MDIM * 4;   // bytes

    ull acc[HEADS][2];
#pragma unroll
    for (int h = 0; h < HEADS; h++) { acc[h][0] = 0ull; acc[h][1] = 0ull; }

    ull bx[4], by[4];
#pragma unroll
    for (int i = 0; i < 4; i++) ldcs_v2u64(pe + (size_t)i * PLANE, bx[i], by[i]);

    for (int eo = 0; eo < EMB; eo += 4) {
#pragma unroll
        for (int i = 0; i < 4; i++) {
            ull pvx = bx[i], pvy = by[i];
            int en_ = eo + 4 + i;
            if (en_ < EMB) ldcs_v2u64(pe + (size_t)en_ * PLANE, bx[i], by[i]);
            const ulonglong2* wrow = (const ulonglong2*)sh_wg2[eo + i];
#pragma unroll
            for (int h2 = 0; h2 < 8; h2++) {
                ulonglong2 w = wrow[h2];          // LDS.128: 2 heads
                fma2(acc[2 * h2][0],     w.x, pvx);
                fma2(acc[2 * h2][1],     w.x, pvy);
                fma2(acc[2 * h2 + 1][0], w.y, pvx);
                fma2(acc[2 * h2 + 1][1], w.y, pvy);
            }
        }
    }

    const float4 av = *(const float4*)&g_aff[(size_t)n * MDIM + m];
    const float L2E = 1.4426950408889634f;
    float en0 = exp2f(-av.x * L2E);
    float en1 = exp2f(-av.y * L2E);
    float en2 = exp2f(-av.z * L2E);
    float en3 = exp2f(-av.w * L2E);

    float s0 = 0.f, s1 = 0.f, s2 = 0.f, s3 = 0.f;
#pragma unroll
    for (int h = 0; h < HEADS; h++) {
        float bh = sh_b[h];
        float2 p0 = unpack2(acc[h][0]);
        float2 p1 = unpack2(acc[h][1]);
        float w;
        w = fmaxf(p0.x + bh, 0.f) + 1e-6f; s0 += __fdividef(w, w + en0);
        w = fmaxf(p0.y + bh, 0.f) + 1e-6f; s1 += __fdividef(w, w + en1);
        w = fmaxf(p1.x + bh, 0.f) + 1e-6f; s2 += __fdividef(w, w + en2);
        w = fmaxf(p1.y + bh, 0.f) + 1e-6f; s3 += __fdividef(w, w + en3);
    }

    float4 o;
    o.x = (s0 > 8.0f) ? 1.0f : 0.0f;
    o.y = (s1 > 8.0f) ? 1.0f : 0.0f;
    o.z = (s2 > 8.0f) ? 1.0f : 0.0f;
    o.w = (s3 > 8.0f) ? 1.0f : 0.0f;
    *(float4*)&out[(size_t)n * MDIM + m] = o;
}

// ---------------------------------------------------------------------------
extern "C" void kernel_launch(void* const* d_in, const int* in_sizes, int n_in,
                              void* d_out, int out_size)
{
    (void)in_sizes; (void)n_in; (void)out_size;
    const float* ref_feat = (const float*)d_in[0];
    const float* sup_feat = (const float*)d_in[1];
    const float* PE       = (const float*)d_in[2];
    const float* Wg_w     = (const float*)d_in[3];
    const float* Wg_b     = (const float*)d_in[4];
    const float* Wq_w     = (const float*)d_in[5];
    const float* Wq_b     = (const float*)d_in[6];
    const float* Wk_w     = (const float*)d_in[7];
    const float* Wk_b     = (const float*)d_in[8];
    float* out = (float*)d_out;

    // fused q/k GEMM: z=0 -> q = ref@WqT+bq, z=1 -> k = sup@WkT+bk
    gemm_nt_kernel<<<dim3(DDIM / BN, NDIM / BM, 2), 512>>>(
        ref_feat, Wq_w, Wq_b, sup_feat, Wk_w, Wk_b, DDIM, 1.0f, 0);
    // aff = (q @ kT) / 32
    gemm_nt_kernel<<<dim3(MDIM / BN, NDIM / BM, 1), 512>>>(
        nullptr, nullptr, nullptr, nullptr, nullptr, nullptr, MDIM, 0.03125f, 2);
    // pos stream + fused epilogue
    pos_epilogue_kernel<<<dim3(MDIM / 1024, NDIM), 256>>>(PE, Wg_w, Wg_b, out);
}